// round 14
// baseline (speedup 1.0000x reference)
#include <cuda_runtime.h>
#include <cuda_fp16.h>
#include <cstdint>

// ===========================================================================
// Cross_26998164423018  (B=8, N=2048, C=576, H=1)
// Round 14: R11 design with FIXED stage loader (6 cp.async chunks/thread =
// full A+B tiles). 64x128 CTA tile, 32x32 warp tile, 2-stage BK=64,
// 3 CTA/SM target. fp16 m16n8k16.
// ===========================================================================

#define CDIM   576
#define NTOK   2048
#define BATCH  8
#define ROWS   (BATCH * NTOK)          // 16384
#define ATT_SCALE 0.0416666679f        // 1/24

#define ROW_BYTES   144                // 64 data halves (128B) + 8 pad
#define ROW_U32     36
#define A_TILE      (64 * ROW_BYTES)               // 9216
#define B_TILE      (128 * ROW_BYTES)              // 18432
#define STAGE_BYTES (A_TILE + B_TILE)              // 27648
#define SMEM_SZ     (2 * STAGE_BYTES)              // 55296 (3 CTA/SM)
#define EH          136                // half epilogue stride (n-major)
#define ET          72                 // half epilogue stride (transposed)
#define EF          132                // float epilogue stride

// ------------------------- scratch (static device mem) ---------------------
__device__ float  g_xnf[(size_t)ROWS * CDIM];      // fp32 xn (residual)
__device__ __half g_xnh[(size_t)ROWS * CDIM];
__device__ __half g_ynh[(size_t)ROWS * CDIM];
__device__ __half g_wq [(size_t)CDIM * CDIM];
__device__ __half g_wk [(size_t)CDIM * CDIM];
__device__ __half g_wv [(size_t)CDIM * CDIM];
__device__ __half g_wp [(size_t)CDIM * CDIM];
__device__ __half g_q  [(size_t)ROWS * CDIM];
__device__ __half g_k  [(size_t)ROWS * CDIM];
__device__ __half g_vt [(size_t)BATCH * CDIM * NTOK];   // [b][n][t]
__device__ __half g_o  [(size_t)ROWS * CDIM];
__device__ __half g_attn[(size_t)BATCH * NTOK * NTOK];  // 67 MB
__device__ float  g_p  [(size_t)ROWS * CDIM];

// ------------------------------- helpers -----------------------------------
__device__ __forceinline__ uint32_t smem_u32(const void* p) {
    uint32_t a;
    asm("{ .reg .u64 t; cvta.to.shared.u64 t, %1; cvt.u32.u64 %0, t; }"
        : "=r"(a) : "l"(p));
    return a;
}
__device__ __forceinline__ void cpa16(uint32_t dst, const void* src, uint32_t sz) {
    asm volatile("cp.async.cg.shared.global [%0], [%1], 16, %2;"
                 :: "r"(dst), "l"(src), "r"(sz) : "memory");
}
__device__ __forceinline__ void cpa_commit() {
    asm volatile("cp.async.commit_group;" ::: "memory");
}
template<int Np> __device__ __forceinline__ void cpa_wait() {
    asm volatile("cp.async.wait_group %0;" :: "n"(Np) : "memory");
}
__device__ __forceinline__ void mma_f16(float* c, const uint32_t* a, const uint32_t* b) {
    asm volatile(
        "mma.sync.aligned.m16n8k16.row.col.f32.f16.f16.f32 "
        "{%0,%1,%2,%3}, {%4,%5,%6,%7}, {%8,%9}, {%0,%1,%2,%3};"
        : "+f"(c[0]), "+f"(c[1]), "+f"(c[2]), "+f"(c[3])
        : "r"(a[0]), "r"(a[1]), "r"(a[2]), "r"(a[3]), "r"(b[0]), "r"(b[1]));
}

// ---------------------------------------------------------------------------
// Main loop: 64(m) x 128(n) CTA tile, BK=64, 2 stages, 8 warps (2x4),
// warp tile 32x32 (acc[2][4][4]).
// Loader: A row tid>>2 / 16-half chunk (tid&3)  -> 2 cpa16
//         B row tid>>1 / 32-half chunk (tid&1)  -> 4 cpa16
// ---------------------------------------------------------------------------
struct LoopCtx {
    const __half* aPtr;
    const __half* bPtr;
    uint32_t dA, dB, bsz;
};

__device__ __forceinline__ void gemm_loop(
    const LoopCtx& cx, char* smem, int KT,
    int arow, int brow, int tig, float acc[2][4][4])
{
    auto load_stage = [&](int s, int kt) {
        const uint32_t so = (uint32_t)s * STAGE_BYTES;
        const int k0 = kt * 64;
        cpa16(cx.dA + so,      cx.aPtr + k0,     16u);
        cpa16(cx.dA + so + 16, cx.aPtr + k0 + 8, 16u);
        #pragma unroll
        for (int j = 0; j < 4; j++)
            cpa16(cx.dB + so + j * 16, cx.bPtr + k0 + j * 8, cx.bsz);
    };

    load_stage(0, 0); cpa_commit();
    load_stage(1, 1); cpa_commit();

    for (int kt = 0; kt < KT; kt++) {
        cpa_wait<1>();
        __syncthreads();                 // stage kt&1 landed

        const uint32_t* uAs = (const uint32_t*)(smem + (kt & 1) * STAGE_BYTES);
        const uint32_t* uBs = uAs + 64 * ROW_U32;

        #pragma unroll
        for (int kk = 0; kk < 4; kk++) {
            const int kc = kk * 8 + tig;
            uint32_t af[2][4];
            #pragma unroll
            for (int mt = 0; mt < 2; mt++) {
                const int r = arow + mt * 16;
                af[mt][0] = uAs[r * ROW_U32 + kc];
                af[mt][1] = uAs[(r + 8) * ROW_U32 + kc];
                af[mt][2] = uAs[r * ROW_U32 + kc + 4];
                af[mt][3] = uAs[(r + 8) * ROW_U32 + kc + 4];
            }
            uint32_t bf[4][2];
            #pragma unroll
            for (int nt = 0; nt < 4; nt++) {
                const int n = brow + nt * 8;
                bf[nt][0] = uBs[n * ROW_U32 + kc];
                bf[nt][1] = uBs[n * ROW_U32 + kc + 4];
            }
            #pragma unroll
            for (int mt = 0; mt < 2; mt++)
                #pragma unroll
                for (int nt = 0; nt < 4; nt++)
                    mma_f16(acc[mt][nt], af[mt], bf[nt]);
        }

        __syncthreads();                 // stage kt&1 fully consumed
        if (kt + 2 < KT) load_stage(kt & 1, kt + 2);
        cpa_commit();
    }

    cpa_wait<0>();
    __syncthreads();
}

// ===========================================================================
// Generic GEMM: C[M,N] = A[M,K] @ B[N,K]^T  (half, K-major)
// grid: (x = N/128-tiles, y = M/64-tiles, z = batch), block = 256
// EPI: 1 = half store, 2 = sigmoid(x/24) half store,
//      3 = fp32 store + bias[n] + resid[m,n]
// ===========================================================================
template<int EPI>
__global__ __launch_bounds__(256, 3) void mma_gemm(
    const __half* __restrict__ A, const __half* __restrict__ B,
    void* __restrict__ Cv, int M, int N, int K,
    long sAz, long sBz, long sCz, int ldC,
    const float* __restrict__ bias, const float* __restrict__ resid)
{
    extern __shared__ char smem[];
    const uint32_t sb = smem_u32(smem);
    const int tid  = threadIdx.x;
    const int lane = tid & 31;
    const int wid  = tid >> 5;
    const int m0 = blockIdx.y * 64;
    const int n0 = blockIdx.x * 128;
    const int z  = blockIdx.z;

    const int gnB = n0 + (tid >> 1);
    LoopCtx cx;
    cx.aPtr = A + (size_t)z * sAz + (size_t)(m0 + (tid >> 2)) * K + (tid & 3) * 16;
    cx.bsz  = (gnB < N) ? 16u : 0u;
    cx.bPtr = B + (size_t)z * sBz + (size_t)(gnB < N ? gnB : 0) * K + (tid & 1) * 32;
    cx.dA   = sb + (uint32_t)(tid >> 2) * ROW_BYTES + (uint32_t)(tid & 3) * 32;
    cx.dB   = sb + A_TILE + (uint32_t)(tid >> 1) * ROW_BYTES + (uint32_t)(tid & 1) * 64;

    float acc[2][4][4];
    #pragma unroll
    for (int mt = 0; mt < 2; mt++)
        #pragma unroll
        for (int nt = 0; nt < 4; nt++)
            #pragma unroll
            for (int i = 0; i < 4; i++) acc[mt][nt][i] = 0.f;

    const int warp_m = wid & 1;
    const int warp_n = wid >> 1;
    const int gid = lane >> 2;
    const int tig = lane & 3;

    gemm_loop(cx, smem, K >> 6, warp_m * 32 + gid, warp_n * 32 + gid, tig, acc);

    // -------------------------------- epilogue --------------------------------
    if (EPI == 3) {
        float* eb = (float*)smem;        // [64][EF]
        #pragma unroll
        for (int mt = 0; mt < 2; mt++)
            #pragma unroll
            for (int i = 0; i < 4; i++) {
                const int r = warp_m * 32 + mt * 16 + gid + ((i >= 2) ? 8 : 0);
                #pragma unroll
                for (int nt = 0; nt < 4; nt++) {
                    const int c = warp_n * 32 + nt * 8 + tig * 2 + (i & 1);
                    eb[r * EF + c] = acc[mt][nt][i];
                }
            }
        __syncthreads();
        float* C = (float*)Cv;
        #pragma unroll
        for (int it = 0; it < 8; it++) {
            const int lin = it * 256 + tid;
            const int c4 = lin & 31, r = lin >> 5;    // r 0..63
            const int n = n0 + c4 * 4;
            if (n < N) {
                float4 v4 = *(const float4*)(eb + r * EF + c4 * 4);
                const float4 bb = *(const float4*)(bias + n);
                const float4 rr = *(const float4*)(resid + (size_t)(m0 + r) * ldC + n);
                v4.x += bb.x + rr.x; v4.y += bb.y + rr.y;
                v4.z += bb.z + rr.z; v4.w += bb.w + rr.w;
                *(float4*)(C + (size_t)(m0 + r) * ldC + n) = v4;
            }
        }
        return;
    }

    __half* ebh = (__half*)smem;         // [64][EH]
    #pragma unroll
    for (int mt = 0; mt < 2; mt++)
        #pragma unroll
        for (int ih = 0; ih < 2; ih++) {
            const int r = warp_m * 32 + mt * 16 + gid + ih * 8;
            #pragma unroll
            for (int nt = 0; nt < 4; nt++) {
                const int c = warp_n * 32 + nt * 8 + tig * 2;
                float v0 = acc[mt][nt][ih * 2], v1 = acc[mt][nt][ih * 2 + 1];
                if (EPI == 2) {
                    v0 = 1.0f / (1.0f + __expf(-v0 * ATT_SCALE));
                    v1 = 1.0f / (1.0f + __expf(-v1 * ATT_SCALE));
                }
                *(__half2*)(ebh + r * EH + c) = __floats2half2_rn(v0, v1);
            }
        }
    __syncthreads();
    {
        __half* C = (__half*)Cv + (size_t)z * sCz;
        #pragma unroll
        for (int it = 0; it < 4; it++) {
            const int lin = it * 256 + tid;
            const int c8 = lin & 15, r = lin >> 4;    // r 0..63
            const int n = n0 + c8 * 8;
            if (n < N)
                *(uint4*)(C + (size_t)(m0 + r) * ldC + n) =
                    *(const uint4*)(ebh + r * EH + c8 * 8);
        }
    }
}

// ===========================================================================
// Fused QKV projection: grid (5, 256, 3); z = 0:q, 1:k, 2:vt(transposed)
// ===========================================================================
__global__ __launch_bounds__(256, 3) void proj_gemm(
    const __half* __restrict__ xnh, const __half* __restrict__ ynh,
    const __half* __restrict__ wq, const __half* __restrict__ wk,
    const __half* __restrict__ wv,
    __half* __restrict__ q, __half* __restrict__ k, __half* __restrict__ vt)
{
    extern __shared__ char smem[];
    const uint32_t sb = smem_u32(smem);
    const int tid  = threadIdx.x;
    const int lane = tid & 31;
    const int wid  = tid >> 5;
    const int m0 = blockIdx.y * 64;
    const int n0 = blockIdx.x * 128;
    const int z  = blockIdx.z;

    const __half* A = (z == 0) ? ynh : xnh;
    const __half* B = (z == 0) ? wq : (z == 1) ? wk : wv;

    const int gnB = n0 + (tid >> 1);
    LoopCtx cx;
    cx.aPtr = A + (size_t)(m0 + (tid >> 2)) * CDIM + (tid & 3) * 16;
    cx.bsz  = (gnB < CDIM) ? 16u : 0u;
    cx.bPtr = B + (size_t)(gnB < CDIM ? gnB : 0) * CDIM + (tid & 1) * 32;
    cx.dA   = sb + (uint32_t)(tid >> 2) * ROW_BYTES + (uint32_t)(tid & 3) * 32;
    cx.dB   = sb + A_TILE + (uint32_t)(tid >> 1) * ROW_BYTES + (uint32_t)(tid & 1) * 64;

    float acc[2][4][4];
    #pragma unroll
    for (int mt = 0; mt < 2; mt++)
        #pragma unroll
        for (int nt = 0; nt < 4; nt++)
            #pragma unroll
            for (int i = 0; i < 4; i++) acc[mt][nt][i] = 0.f;

    const int warp_m = wid & 1;
    const int warp_n = wid >> 1;
    const int gid = lane >> 2;
    const int tig = lane & 3;

    gemm_loop(cx, smem, CDIM >> 6, warp_m * 32 + gid, warp_n * 32 + gid, tig, acc);

    __half* ebh = (__half*)smem;
    if (z == 2) {
        // transposed staging: ebh[n_local][t_local] (stride ET=72)
        #pragma unroll
        for (int mt = 0; mt < 2; mt++)
            #pragma unroll
            for (int i = 0; i < 4; i++) {
                const int r = warp_m * 32 + mt * 16 + gid + ((i >= 2) ? 8 : 0);
                #pragma unroll
                for (int nt = 0; nt < 4; nt++) {
                    const int c = warp_n * 32 + nt * 8 + tig * 2 + (i & 1);
                    ebh[c * ET + r] = __float2half_rn(acc[mt][nt][i]);
                }
            }
        __syncthreads();
        const int b = m0 >> 11, t0 = m0 & 2047;
        __half* vb = vt + (size_t)b * CDIM * NTOK + t0;
        #pragma unroll
        for (int it = 0; it < 4; it++) {
            const int lin = it * 256 + tid;
            const int t8 = (lin & 7) * 8, n = lin >> 3;   // n 0..127
            if (n0 + n < CDIM)
                *(uint4*)(vb + (size_t)(n0 + n) * NTOK + t8) =
                    *(const uint4*)(ebh + n * ET + t8);
        }
        return;
    }

    #pragma unroll
    for (int mt = 0; mt < 2; mt++)
        #pragma unroll
        for (int ih = 0; ih < 2; ih++) {
            const int r = warp_m * 32 + mt * 16 + gid + ih * 8;
            #pragma unroll
            for (int nt = 0; nt < 4; nt++) {
                const int c = warp_n * 32 + nt * 8 + tig * 2;
                *(__half2*)(ebh + r * EH + c) =
                    __floats2half2_rn(acc[mt][nt][ih * 2], acc[mt][nt][ih * 2 + 1]);
            }
        }
    __syncthreads();
    {
        __half* C = (z == 0) ? q : k;
        #pragma unroll
        for (int it = 0; it < 4; it++) {
            const int lin = it * 256 + tid;
            const int c8 = lin & 15, r = lin >> 4;
            const int n = n0 + c8 * 8;
            if (n < CDIM)
                *(uint4*)(C + (size_t)(m0 + r) * CDIM + n) =
                    *(const uint4*)(ebh + r * EH + c8 * 8);
        }
    }
}

// ===========================================================================
// LayerNorm over 576; writes fp32 and/or half output.
// ===========================================================================
__global__ __launch_bounds__(256) void ln_kernel(
    const float* __restrict__ x, const float* __restrict__ g,
    const float* __restrict__ b, float* __restrict__ out_f,
    __half* __restrict__ out_h)
{
    const long row = blockIdx.x;
    const float* xr = x + row * (long)CDIM;
    const int t = threadIdx.x;

    float v0 = xr[t];
    float v1 = xr[t + 256];
    float v2 = (t < 64) ? xr[t + 512] : 0.f;

    float s  = v0 + v1 + v2;
    float ss = v0 * v0 + v1 * v1 + v2 * v2;
    #pragma unroll
    for (int o = 16; o > 0; o >>= 1) {
        s  += __shfl_xor_sync(0xFFFFFFFFu, s,  o);
        ss += __shfl_xor_sync(0xFFFFFFFFu, ss, o);
    }
    __shared__ float sh_s[8], sh_ss[8];
    const int w = t >> 5, l = t & 31;
    if (l == 0) { sh_s[w] = s; sh_ss[w] = ss; }
    __syncthreads();
    float stot = 0.f, sstot = 0.f;
    #pragma unroll
    for (int i = 0; i < 8; i++) { stot += sh_s[i]; sstot += sh_ss[i]; }

    const float inv_n = 1.0f / (float)CDIM;
    const float mean = stot * inv_n;
    const float var  = sstot * inv_n - mean * mean;
    const float rstd = rsqrtf(var + 1e-5f);

    float o0 = (v0 - mean) * rstd * g[t]       + b[t];
    float o1 = (v1 - mean) * rstd * g[t + 256] + b[t + 256];
    float o2 = (t < 64) ? ((v2 - mean) * rstd * g[t + 512] + b[t + 512]) : 0.f;

    if (out_f) {
        out_f[row * (long)CDIM + t]       = o0;
        out_f[row * (long)CDIM + t + 256] = o1;
        if (t < 64) out_f[row * (long)CDIM + t + 512] = o2;
    }
    if (out_h) {
        out_h[row * (long)CDIM + t]       = __float2half_rn(o0);
        out_h[row * (long)CDIM + t + 256] = __float2half_rn(o1);
        if (t < 64) out_h[row * (long)CDIM + t + 512] = __float2half_rn(o2);
    }
}

// all 4 weight matrices in one launch; float4 -> 2x half2 per thread
__global__ void h_convert4(
    const float* __restrict__ s0, const float* __restrict__ s1,
    const float* __restrict__ s2, const float* __restrict__ s3,
    __half* __restrict__ d0, __half* __restrict__ d1,
    __half* __restrict__ d2, __half* __restrict__ d3, int n4)
{
    const int i = blockIdx.x * blockDim.x + threadIdx.x;
    if (i >= 4 * n4) return;
    const int sel = i / n4, j = i - sel * n4;
    const float* src = (sel == 0) ? s0 : (sel == 1) ? s1 : (sel == 2) ? s2 : s3;
    __half* dst      = (sel == 0) ? d0 : (sel == 1) ? d1 : (sel == 2) ? d2 : d3;
    const float4 v = *(const float4*)(src + j * 4);
    *(__half2*)(dst + j * 4)     = __floats2half2_rn(v.x, v.y);
    *(__half2*)(dst + j * 4 + 2) = __floats2half2_rn(v.z, v.w);
}

// ===========================================================================
extern "C" void kernel_launch(void* const* d_in, const int* in_sizes, int n_in,
                              void* d_out, int out_size)
{
    const float* x  = (const float*)d_in[0];
    const float* y  = (const float*)d_in[1];
    const float* Wq = (const float*)d_in[2];
    const float* Wk = (const float*)d_in[3];
    const float* Wv = (const float*)d_in[4];
    const float* Wp = (const float*)d_in[5];
    const float* bp = (const float*)d_in[6];
    const float* gx = (const float*)d_in[7];
    const float* bx = (const float*)d_in[8];
    const float* gy = (const float*)d_in[9];
    const float* by = (const float*)d_in[10];
    const float* gz = (const float*)d_in[11];
    const float* bz = (const float*)d_in[12];
    float* out = (float*)d_out;

    float *xnf, *p;
    __half *xnh, *ynh, *wq, *wk, *wv, *wp, *q, *k, *vt, *o, *attn;
    cudaGetSymbolAddress((void**)&xnf, g_xnf);
    cudaGetSymbolAddress((void**)&xnh, g_xnh);
    cudaGetSymbolAddress((void**)&ynh, g_ynh);
    cudaGetSymbolAddress((void**)&wq,  g_wq);
    cudaGetSymbolAddress((void**)&wk,  g_wk);
    cudaGetSymbolAddress((void**)&wv,  g_wv);
    cudaGetSymbolAddress((void**)&wp,  g_wp);
    cudaGetSymbolAddress((void**)&q,   g_q);
    cudaGetSymbolAddress((void**)&k,   g_k);
    cudaGetSymbolAddress((void**)&vt,  g_vt);
    cudaGetSymbolAddress((void**)&o,   g_o);
    cudaGetSymbolAddress((void**)&attn,g_attn);
    cudaGetSymbolAddress((void**)&p,   g_p);

    cudaFuncSetAttribute(mma_gemm<1>, cudaFuncAttributeMaxDynamicSharedMemorySize, SMEM_SZ);
    cudaFuncSetAttribute(mma_gemm<2>, cudaFuncAttributeMaxDynamicSharedMemorySize, SMEM_SZ);
    cudaFuncSetAttribute(mma_gemm<3>, cudaFuncAttributeMaxDynamicSharedMemorySize, SMEM_SZ);
    cudaFuncSetAttribute(proj_gemm,   cudaFuncAttributeMaxDynamicSharedMemorySize, SMEM_SZ);

    // 1. LayerNorms (fp32 residual copy + half operand copy)
    ln_kernel<<<ROWS, 256>>>(x, gx, bx, xnf, xnh);
    ln_kernel<<<ROWS, 256>>>(y, gy, by, nullptr, ynh);

    // 2. weights -> half (single launch)
    {
        const int n4 = CDIM * CDIM / 4;
        const int nb = (4 * n4 + 255) / 256;
        h_convert4<<<nb, 256>>>(Wq, Wk, Wv, Wp, wq, wk, wv, wp, n4);
    }

    // 3. fused projections: z=0 q, z=1 k, z=2 vt
    {
        dim3 grid(5, 256, 3);
        proj_gemm<<<grid, 256, SMEM_SZ>>>(xnh, ynh, wq, wk, wv, q, k, vt);
    }

    // 4. attn = sigmoid(q @ k^T / 24) per batch, half
    {
        dim3 grid(16, 32, BATCH);
        mma_gemm<2><<<grid, 256, SMEM_SZ>>>(q, k, attn, NTOK, NTOK, CDIM,
            (long)NTOK * CDIM, (long)NTOK * CDIM, (long)NTOK * NTOK, NTOK, nullptr, nullptr);
    }

    // 5. O = attn @ Vt^T per batch (M=2048, N=576, K=2048)
    {
        dim3 grid(5, 32, BATCH);
        mma_gemm<1><<<grid, 256, SMEM_SZ>>>(attn, vt, o, NTOK, CDIM, NTOK,
            (long)NTOK * NTOK, (long)CDIM * NTOK, (long)NTOK * CDIM, CDIM, nullptr, nullptr);
    }

    // 6. P = O @ Wp^T + bp + xn_full  (fp32 out)
    {
        dim3 grid(5, 256, 1);
        mma_gemm<3><<<grid, 256, SMEM_SZ>>>(o, wp, p, ROWS, CDIM, CDIM, 0, 0, 0, CDIM, bp, xnf);
    }

    // 7. out = LN(P)
    ln_kernel<<<ROWS, 256>>>(p, gz, bz, out, nullptr);
}

// round 15
// speedup vs baseline: 1.1154x; 1.1154x over previous
#include <cuda_runtime.h>
#include <cuda_fp16.h>
#include <cstdint>

// ===========================================================================
// Cross_26998164423018  (B=8, N=2048, C=576, H=1)
// Round 15: R8 proven core (128x128 tile, BK=64, 2-stage cp.async, fp16
// m16n8k16 scalar-LDS loop) + fused QKV projection launch + fused dual-LN.
// ===========================================================================

#define CDIM   576
#define NTOK   2048
#define BATCH  8
#define ROWS   (BATCH * NTOK)          // 16384
#define ATT_SCALE 0.0416666679f        // 1/24

#define ROW_BYTES   144                // 64 data halves (128B) + 16 pad
#define ROW_U32     36
#define TILE_BYTES  (128 * ROW_BYTES)               // 18432
#define STAGE_BYTES (2 * TILE_BYTES)                // A+B = 36864
#define EH          136                // half epilogue stride
#define EF          132                // float epilogue stride
#define SMEM_SZ     (2 * STAGE_BYTES)               // 73728 (2 CTA/SM)

// ------------------------- scratch (static device mem) ---------------------
__device__ float  g_xnf[(size_t)ROWS * CDIM];      // fp32 xn (residual)
__device__ __half g_xnh[(size_t)ROWS * CDIM];
__device__ __half g_ynh[(size_t)ROWS * CDIM];
__device__ __half g_wq [(size_t)CDIM * CDIM];
__device__ __half g_wk [(size_t)CDIM * CDIM];
__device__ __half g_wv [(size_t)CDIM * CDIM];
__device__ __half g_wp [(size_t)CDIM * CDIM];
__device__ __half g_q  [(size_t)ROWS * CDIM];
__device__ __half g_k  [(size_t)ROWS * CDIM];
__device__ __half g_vt [(size_t)BATCH * CDIM * NTOK];   // [b][n][t]
__device__ __half g_o  [(size_t)ROWS * CDIM];
__device__ __half g_attn[(size_t)BATCH * NTOK * NTOK];  // 67 MB
__device__ float  g_p  [(size_t)ROWS * CDIM];

// ------------------------------- helpers -----------------------------------
__device__ __forceinline__ uint32_t smem_u32(const void* p) {
    uint32_t a;
    asm("{ .reg .u64 t; cvta.to.shared.u64 t, %1; cvt.u32.u64 %0, t; }"
        : "=r"(a) : "l"(p));
    return a;
}
__device__ __forceinline__ void cpa16(uint32_t dst, const void* src, uint32_t sz) {
    asm volatile("cp.async.cg.shared.global [%0], [%1], 16, %2;"
                 :: "r"(dst), "l"(src), "r"(sz) : "memory");
}
__device__ __forceinline__ void cpa_commit() {
    asm volatile("cp.async.commit_group;" ::: "memory");
}
template<int Np> __device__ __forceinline__ void cpa_wait() {
    asm volatile("cp.async.wait_group %0;" :: "n"(Np) : "memory");
}
__device__ __forceinline__ void mma_f16(float* c, const uint32_t* a, const uint32_t* b) {
    asm volatile(
        "mma.sync.aligned.m16n8k16.row.col.f32.f16.f16.f32 "
        "{%0,%1,%2,%3}, {%4,%5,%6,%7}, {%8,%9}, {%0,%1,%2,%3};"
        : "+f"(c[0]), "+f"(c[1]), "+f"(c[2]), "+f"(c[3])
        : "r"(a[0]), "r"(a[1]), "r"(a[2]), "r"(a[3]), "r"(b[0]), "r"(b[1]));
}

// ---------------------------------------------------------------------------
// R8 main loop: 128x128 CTA tile, BK=64, 2 stages, 8 warps (2x4),
// warp tile 64x32 (acc[4][4][4]). Loader: row tid>>1, 32-half chunk tid&1
// (4 cpa16 each for A and B).
// ---------------------------------------------------------------------------
struct LoopCtx {
    const __half* aPtr;
    const __half* bPtr;
    uint32_t dA, dB, bsz;
};

__device__ __forceinline__ void gemm_loop(
    const LoopCtx& cx, char* smem, int KT,
    int arow, int brow, int tig, float acc[4][4][4])
{
    auto load_stage = [&](int s, int kt) {
        const uint32_t so = (uint32_t)s * STAGE_BYTES;
        const int k0 = kt * 64;
        #pragma unroll
        for (int j = 0; j < 4; j++) {
            cpa16(cx.dA + so + j * 16, cx.aPtr + k0 + j * 8, 16u);
            cpa16(cx.dB + so + j * 16, cx.bPtr + k0 + j * 8, cx.bsz);
        }
    };

    load_stage(0, 0); cpa_commit();
    load_stage(1, 1); cpa_commit();

    for (int kt = 0; kt < KT; kt++) {
        cpa_wait<1>();
        __syncthreads();                 // stage kt&1 landed

        const uint32_t* uAs = (const uint32_t*)(smem + (kt & 1) * STAGE_BYTES);
        const uint32_t* uBs = uAs + 128 * ROW_U32;

        #pragma unroll
        for (int kk = 0; kk < 4; kk++) {
            const int kc = kk * 8 + tig;
            uint32_t af[4][4];
            #pragma unroll
            for (int mt = 0; mt < 4; mt++) {
                const int r = arow + mt * 16;
                af[mt][0] = uAs[r * ROW_U32 + kc];
                af[mt][1] = uAs[(r + 8) * ROW_U32 + kc];
                af[mt][2] = uAs[r * ROW_U32 + kc + 4];
                af[mt][3] = uAs[(r + 8) * ROW_U32 + kc + 4];
            }
            uint32_t bf[4][2];
            #pragma unroll
            for (int nt = 0; nt < 4; nt++) {
                const int n = brow + nt * 8;
                bf[nt][0] = uBs[n * ROW_U32 + kc];
                bf[nt][1] = uBs[n * ROW_U32 + kc + 4];
            }
            #pragma unroll
            for (int mt = 0; mt < 4; mt++)
                #pragma unroll
                for (int nt = 0; nt < 4; nt++)
                    mma_f16(acc[mt][nt], af[mt], bf[nt]);
        }

        __syncthreads();                 // stage kt&1 fully consumed
        if (kt + 2 < KT) load_stage(kt & 1, kt + 2);
        cpa_commit();
    }

    cpa_wait<0>();
    __syncthreads();
}

// ===========================================================================
// Generic GEMM: C[M,N] = A[M,K] @ B[N,K]^T  (half, K-major)
// grid: (x = N/128-tiles, y = M/128-tiles, z = batch), block = 256
// EPI: 1 = half store, 2 = sigmoid(x/24) half store,
//      3 = fp32 store + bias[n] + resid[m,n]
// ===========================================================================
template<int EPI>
__global__ __launch_bounds__(256, 2) void mma_gemm(
    const __half* __restrict__ A, const __half* __restrict__ B,
    void* __restrict__ Cv, int M, int N, int K,
    long sAz, long sBz, long sCz, int ldC,
    const float* __restrict__ bias, const float* __restrict__ resid)
{
    extern __shared__ char smem[];
    const uint32_t sb = smem_u32(smem);
    const int tid  = threadIdx.x;
    const int lane = tid & 31;
    const int wid  = tid >> 5;
    const int m0 = blockIdx.y * 128;
    const int n0 = blockIdx.x * 128;
    const int z  = blockIdx.z;

    const int lrow  = tid >> 1;
    const int lhalf = tid & 1;
    const int gn = n0 + lrow;
    LoopCtx cx;
    cx.aPtr = A + (size_t)z * sAz + (size_t)(m0 + lrow) * K + lhalf * 32;
    cx.bsz  = (gn < N) ? 16u : 0u;
    cx.bPtr = B + (size_t)z * sBz + (size_t)(gn < N ? gn : 0) * K + lhalf * 32;
    cx.dA   = sb + (uint32_t)lrow * ROW_BYTES + (uint32_t)lhalf * 64;
    cx.dB   = cx.dA + TILE_BYTES;

    float acc[4][4][4];
    #pragma unroll
    for (int mt = 0; mt < 4; mt++)
        #pragma unroll
        for (int nt = 0; nt < 4; nt++)
            #pragma unroll
            for (int i = 0; i < 4; i++) acc[mt][nt][i] = 0.f;

    const int warp_m = wid & 1;
    const int warp_n = wid >> 1;
    const int gid = lane >> 2;
    const int tig = lane & 3;

    gemm_loop(cx, smem, K >> 6, warp_m * 64 + gid, warp_n * 32 + gid, tig, acc);

    // -------------------------------- epilogue --------------------------------
    if (EPI == 3) {
        float* eb = (float*)smem;        // [128][EF]
        #pragma unroll
        for (int mt = 0; mt < 4; mt++)
            #pragma unroll
            for (int i = 0; i < 4; i++) {
                const int r = warp_m * 64 + mt * 16 + gid + ((i >= 2) ? 8 : 0);
                #pragma unroll
                for (int nt = 0; nt < 4; nt++) {
                    const int c = warp_n * 32 + nt * 8 + tig * 2 + (i & 1);
                    eb[r * EF + c] = acc[mt][nt][i];
                }
            }
        __syncthreads();
        float* C = (float*)Cv;
        #pragma unroll
        for (int it = 0; it < 16; it++) {
            const int lin = it * 256 + tid;
            const int c4 = lin & 31, r = lin >> 5;
            const int n = n0 + c4 * 4;
            if (n < N) {
                float4 v4 = *(const float4*)(eb + r * EF + c4 * 4);
                const float4 bb = *(const float4*)(bias + n);
                const float4 rr = *(const float4*)(resid + (size_t)(m0 + r) * ldC + n);
                v4.x += bb.x + rr.x; v4.y += bb.y + rr.y;
                v4.z += bb.z + rr.z; v4.w += bb.w + rr.w;
                *(float4*)(C + (size_t)(m0 + r) * ldC + n) = v4;
            }
        }
        return;
    }

    __half* ebh = (__half*)smem;         // [128][EH]
    #pragma unroll
    for (int mt = 0; mt < 4; mt++)
        #pragma unroll
        for (int ih = 0; ih < 2; ih++) {
            const int r = warp_m * 64 + mt * 16 + gid + ih * 8;
            #pragma unroll
            for (int nt = 0; nt < 4; nt++) {
                const int c = warp_n * 32 + nt * 8 + tig * 2;
                float v0 = acc[mt][nt][ih * 2], v1 = acc[mt][nt][ih * 2 + 1];
                if (EPI == 2) {
                    v0 = 1.0f / (1.0f + __expf(-v0 * ATT_SCALE));
                    v1 = 1.0f / (1.0f + __expf(-v1 * ATT_SCALE));
                }
                *(__half2*)(ebh + r * EH + c) = __floats2half2_rn(v0, v1);
            }
        }
    __syncthreads();
    {
        __half* C = (__half*)Cv + (size_t)z * sCz;
        #pragma unroll
        for (int it = 0; it < 8; it++) {
            const int lin = it * 256 + tid;
            const int c8 = lin & 15, r = lin >> 4;
            const int n = n0 + c8 * 8;
            if (n < N)
                *(uint4*)(C + (size_t)(m0 + r) * ldC + n) =
                    *(const uint4*)(ebh + r * EH + c8 * 8);
        }
    }
}

// ===========================================================================
// Fused QKV projection: grid (5, 128, 3); z = 0:q, 1:k, 2:vt(transposed)
// M=ROWS, N=K=CDIM. Same R8 loop/tile as mma_gemm.
// ===========================================================================
__global__ __launch_bounds__(256, 2) void proj_gemm(
    const __half* __restrict__ xnh, const __half* __restrict__ ynh,
    const __half* __restrict__ wq, const __half* __restrict__ wk,
    const __half* __restrict__ wv,
    __half* __restrict__ q, __half* __restrict__ k, __half* __restrict__ vt)
{
    extern __shared__ char smem[];
    const uint32_t sb = smem_u32(smem);
    const int tid  = threadIdx.x;
    const int lane = tid & 31;
    const int wid  = tid >> 5;
    const int m0 = blockIdx.y * 128;
    const int n0 = blockIdx.x * 128;
    const int z  = blockIdx.z;

    const __half* A = (z == 0) ? ynh : xnh;
    const __half* B = (z == 0) ? wq : (z == 1) ? wk : wv;

    const int lrow  = tid >> 1;
    const int lhalf = tid & 1;
    const int gn = n0 + lrow;
    LoopCtx cx;
    cx.aPtr = A + (size_t)(m0 + lrow) * CDIM + lhalf * 32;
    cx.bsz  = (gn < CDIM) ? 16u : 0u;
    cx.bPtr = B + (size_t)(gn < CDIM ? gn : 0) * CDIM + lhalf * 32;
    cx.dA   = sb + (uint32_t)lrow * ROW_BYTES + (uint32_t)lhalf * 64;
    cx.dB   = cx.dA + TILE_BYTES;

    float acc[4][4][4];
    #pragma unroll
    for (int mt = 0; mt < 4; mt++)
        #pragma unroll
        for (int nt = 0; nt < 4; nt++)
            #pragma unroll
            for (int i = 0; i < 4; i++) acc[mt][nt][i] = 0.f;

    const int warp_m = wid & 1;
    const int warp_n = wid >> 1;
    const int gid = lane >> 2;
    const int tig = lane & 3;

    gemm_loop(cx, smem, CDIM >> 6, warp_m * 64 + gid, warp_n * 32 + gid, tig, acc);

    __half* ebh = (__half*)smem;
    if (z == 2) {
        // transposed staging: ebh[n_local][t_local] (stride EH)
        #pragma unroll
        for (int mt = 0; mt < 4; mt++)
            #pragma unroll
            for (int i = 0; i < 4; i++) {
                const int r = warp_m * 64 + mt * 16 + gid + ((i >= 2) ? 8 : 0);
                #pragma unroll
                for (int nt = 0; nt < 4; nt++) {
                    const int c = warp_n * 32 + nt * 8 + tig * 2 + (i & 1);
                    ebh[c * EH + r] = __float2half_rn(acc[mt][nt][i]);
                }
            }
        __syncthreads();
        const int b = m0 >> 11, t0 = m0 & 2047;
        __half* vb = vt + (size_t)b * CDIM * NTOK + t0;
        #pragma unroll
        for (int it = 0; it < 8; it++) {
            const int lin = it * 256 + tid;
            const int t8 = (lin & 15) * 8, n = lin >> 4;
            if (n0 + n < CDIM)
                *(uint4*)(vb + (size_t)(n0 + n) * NTOK + t8) =
                    *(const uint4*)(ebh + n * EH + t8);
        }
        return;
    }

    #pragma unroll
    for (int mt = 0; mt < 4; mt++)
        #pragma unroll
        for (int ih = 0; ih < 2; ih++) {
            const int r = warp_m * 64 + mt * 16 + gid + ih * 8;
            #pragma unroll
            for (int nt = 0; nt < 4; nt++) {
                const int c = warp_n * 32 + nt * 8 + tig * 2;
                *(__half2*)(ebh + r * EH + c) =
                    __floats2half2_rn(acc[mt][nt][ih * 2], acc[mt][nt][ih * 2 + 1]);
            }
        }
    __syncthreads();
    {
        __half* C = (z == 0) ? q : k;
        #pragma unroll
        for (int it = 0; it < 8; it++) {
            const int lin = it * 256 + tid;
            const int c8 = lin & 15, r = lin >> 4;
            const int n = n0 + c8 * 8;
            if (n < CDIM)
                *(uint4*)(C + (size_t)(m0 + r) * CDIM + n) =
                    *(const uint4*)(ebh + r * EH + c8 * 8);
        }
    }
}

// ===========================================================================
// Fused dual LayerNorm: grid (ROWS, 2). y=0: x -> (xnf, xnh); y=1: y -> ynh.
// ===========================================================================
__global__ __launch_bounds__(256) void ln2_kernel(
    const float* __restrict__ x, const float* __restrict__ y,
    const float* __restrict__ gx, const float* __restrict__ bx,
    const float* __restrict__ gy, const float* __restrict__ by,
    float* __restrict__ xnf, __half* __restrict__ xnh,
    __half* __restrict__ ynh)
{
    const int which = blockIdx.y;
    const long row = blockIdx.x;
    const float* xr = ((which == 0) ? x : y) + row * (long)CDIM;
    const float* g  = (which == 0) ? gx : gy;
    const float* b  = (which == 0) ? bx : by;
    const int t = threadIdx.x;

    float v0 = xr[t];
    float v1 = xr[t + 256];
    float v2 = (t < 64) ? xr[t + 512] : 0.f;

    float s  = v0 + v1 + v2;
    float ss = v0 * v0 + v1 * v1 + v2 * v2;
    #pragma unroll
    for (int o = 16; o > 0; o >>= 1) {
        s  += __shfl_xor_sync(0xFFFFFFFFu, s,  o);
        ss += __shfl_xor_sync(0xFFFFFFFFu, ss, o);
    }
    __shared__ float sh_s[8], sh_ss[8];
    const int w = t >> 5, l = t & 31;
    if (l == 0) { sh_s[w] = s; sh_ss[w] = ss; }
    __syncthreads();
    float stot = 0.f, sstot = 0.f;
    #pragma unroll
    for (int i = 0; i < 8; i++) { stot += sh_s[i]; sstot += sh_ss[i]; }

    const float inv_n = 1.0f / (float)CDIM;
    const float mean = stot * inv_n;
    const float var  = sstot * inv_n - mean * mean;
    const float rstd = rsqrtf(var + 1e-5f);

    float o0 = (v0 - mean) * rstd * g[t]       + b[t];
    float o1 = (v1 - mean) * rstd * g[t + 256] + b[t + 256];
    float o2 = (t < 64) ? ((v2 - mean) * rstd * g[t + 512] + b[t + 512]) : 0.f;

    if (which == 0) {
        xnf[row * (long)CDIM + t]       = o0;
        xnf[row * (long)CDIM + t + 256] = o1;
        if (t < 64) xnf[row * (long)CDIM + t + 512] = o2;
        xnh[row * (long)CDIM + t]       = __float2half_rn(o0);
        xnh[row * (long)CDIM + t + 256] = __float2half_rn(o1);
        if (t < 64) xnh[row * (long)CDIM + t + 512] = __float2half_rn(o2);
    } else {
        ynh[row * (long)CDIM + t]       = __float2half_rn(o0);
        ynh[row * (long)CDIM + t + 256] = __float2half_rn(o1);
        if (t < 64) ynh[row * (long)CDIM + t + 512] = __float2half_rn(o2);
    }
}

// Final LayerNorm: fp32 in -> fp32 out
__global__ __launch_bounds__(256) void ln_kernel(
    const float* __restrict__ x, const float* __restrict__ g,
    const float* __restrict__ b, float* __restrict__ out_f)
{
    const long row = blockIdx.x;
    const float* xr = x + row * (long)CDIM;
    const int t = threadIdx.x;

    float v0 = xr[t];
    float v1 = xr[t + 256];
    float v2 = (t < 64) ? xr[t + 512] : 0.f;

    float s  = v0 + v1 + v2;
    float ss = v0 * v0 + v1 * v1 + v2 * v2;
    #pragma unroll
    for (int o = 16; o > 0; o >>= 1) {
        s  += __shfl_xor_sync(0xFFFFFFFFu, s,  o);
        ss += __shfl_xor_sync(0xFFFFFFFFu, ss, o);
    }
    __shared__ float sh_s[8], sh_ss[8];
    const int w = t >> 5, l = t & 31;
    if (l == 0) { sh_s[w] = s; sh_ss[w] = ss; }
    __syncthreads();
    float stot = 0.f, sstot = 0.f;
    #pragma unroll
    for (int i = 0; i < 8; i++) { stot += sh_s[i]; sstot += sh_ss[i]; }

    const float inv_n = 1.0f / (float)CDIM;
    const float mean = stot * inv_n;
    const float var  = sstot * inv_n - mean * mean;
    const float rstd = rsqrtf(var + 1e-5f);

    out_f[row * (long)CDIM + t]       = (v0 - mean) * rstd * g[t]       + b[t];
    out_f[row * (long)CDIM + t + 256] = (v1 - mean) * rstd * g[t + 256] + b[t + 256];
    if (t < 64)
        out_f[row * (long)CDIM + t + 512] = (v2 - mean) * rstd * g[t + 512] + b[t + 512];
}

// all 4 weight matrices in one launch; float4 -> 2x half2 per thread
__global__ void h_convert4(
    const float* __restrict__ s0, const float* __restrict__ s1,
    const float* __restrict__ s2, const float* __restrict__ s3,
    __half* __restrict__ d0, __half* __restrict__ d1,
    __half* __restrict__ d2, __half* __restrict__ d3, int n4)
{
    const int i = blockIdx.x * blockDim.x + threadIdx.x;
    if (i >= 4 * n4) return;
    const int sel = i / n4, j = i - sel * n4;
    const float* src = (sel == 0) ? s0 : (sel == 1) ? s1 : (sel == 2) ? s2 : s3;
    __half* dst      = (sel == 0) ? d0 : (sel == 1) ? d1 : (sel == 2) ? d2 : d3;
    const float4 v = *(const float4*)(src + j * 4);
    *(__half2*)(dst + j * 4)     = __floats2half2_rn(v.x, v.y);
    *(__half2*)(dst + j * 4 + 2) = __floats2half2_rn(v.z, v.w);
}

// ===========================================================================
extern "C" void kernel_launch(void* const* d_in, const int* in_sizes, int n_in,
                              void* d_out, int out_size)
{
    const float* x  = (const float*)d_in[0];
    const float* y  = (const float*)d_in[1];
    const float* Wq = (const float*)d_in[2];
    const float* Wk = (const float*)d_in[3];
    const float* Wv = (const float*)d_in[4];
    const float* Wp = (const float*)d_in[5];
    const float* bp = (const float*)d_in[6];
    const float* gx = (const float*)d_in[7];
    const float* bx = (const float*)d_in[8];
    const float* gy = (const float*)d_in[9];
    const float* by = (const float*)d_in[10];
    const float* gz = (const float*)d_in[11];
    const float* bz = (const float*)d_in[12];
    float* out = (float*)d_out;

    float *xnf, *p;
    __half *xnh, *ynh, *wq, *wk, *wv, *wp, *q, *k, *vt, *o, *attn;
    cudaGetSymbolAddress((void**)&xnf, g_xnf);
    cudaGetSymbolAddress((void**)&xnh, g_xnh);
    cudaGetSymbolAddress((void**)&ynh, g_ynh);
    cudaGetSymbolAddress((void**)&wq,  g_wq);
    cudaGetSymbolAddress((void**)&wk,  g_wk);
    cudaGetSymbolAddress((void**)&wv,  g_wv);
    cudaGetSymbolAddress((void**)&wp,  g_wp);
    cudaGetSymbolAddress((void**)&q,   g_q);
    cudaGetSymbolAddress((void**)&k,   g_k);
    cudaGetSymbolAddress((void**)&vt,  g_vt);
    cudaGetSymbolAddress((void**)&o,   g_o);
    cudaGetSymbolAddress((void**)&attn,g_attn);
    cudaGetSymbolAddress((void**)&p,   g_p);

    cudaFuncSetAttribute(mma_gemm<1>, cudaFuncAttributeMaxDynamicSharedMemorySize, SMEM_SZ);
    cudaFuncSetAttribute(mma_gemm<2>, cudaFuncAttributeMaxDynamicSharedMemorySize, SMEM_SZ);
    cudaFuncSetAttribute(mma_gemm<3>, cudaFuncAttributeMaxDynamicSharedMemorySize, SMEM_SZ);
    cudaFuncSetAttribute(proj_gemm,   cudaFuncAttributeMaxDynamicSharedMemorySize, SMEM_SZ);

    // 1. fused LayerNorms (x -> xnf+xnh, y -> ynh)
    {
        dim3 grid(ROWS, 2, 1);
        ln2_kernel<<<grid, 256>>>(x, y, gx, bx, gy, by, xnf, xnh, ynh);
    }

    // 2. weights -> half (single launch)
    {
        const int n4 = CDIM * CDIM / 4;
        const int nb = (4 * n4 + 255) / 256;
        h_convert4<<<nb, 256>>>(Wq, Wk, Wv, Wp, wq, wk, wv, wp, n4);
    }

    // 3. fused projections: z=0 q, z=1 k, z=2 vt
    {
        dim3 grid(5, 128, 3);
        proj_gemm<<<grid, 256, SMEM_SZ>>>(xnh, ynh, wq, wk, wv, q, k, vt);
    }

    // 4. attn = sigmoid(q @ k^T / 24) per batch, half
    {
        dim3 grid(16, 16, BATCH);
        mma_gemm<2><<<grid, 256, SMEM_SZ>>>(q, k, attn, NTOK, NTOK, CDIM,
            (long)NTOK * CDIM, (long)NTOK * CDIM, (long)NTOK * NTOK, NTOK, nullptr, nullptr);
    }

    // 5. O = attn @ Vt^T per batch (M=2048, N=576, K=2048)
    {
        dim3 grid(5, 16, BATCH);
        mma_gemm<1><<<grid, 256, SMEM_SZ>>>(attn, vt, o, NTOK, CDIM, NTOK,
            (long)NTOK * NTOK, (long)CDIM * NTOK, (long)NTOK * CDIM, CDIM, nullptr, nullptr);
    }

    // 6. P = O @ Wp^T + bp + xn_full  (fp32 out)
    {
        dim3 grid(5, 128, 1);
        mma_gemm<3><<<grid, 256, SMEM_SZ>>>(o, wp, p, ROWS, CDIM, CDIM, 0, 0, 0, CDIM, bp, xnf);
    }

    // 7. out = LN(P)
    ln_kernel<<<ROWS, 256>>>(p, gz, bz, out);
}

// round 17
// speedup vs baseline: 1.2897x; 1.1563x over previous
#include <cuda_runtime.h>
#include <cuda_fp16.h>
#include <cstdint>

// ===========================================================================
// Cross_26998164423018  (B=8, N=2048, C=576, H=1)
// Round 16: algebraic weight folding. attn = sigmoid(yn*(Wq^T Wk)*xn^T /24),
// P = attn*(xn*(Wp*Wv)^T) + bp + xn. Eliminates K-proj and Wp GEMMs.
// Core loop = R8/R15 proven fp16 m16n8k16, BK=64, 2-stage cp.async.
// ===========================================================================

#define CDIM   576
#define CPAD   640                     // 5*128, padded row count for weights
#define NTOK   2048
#define BATCH  8
#define ROWS   (BATCH * NTOK)          // 16384
#define ATT_SCALE 0.0416666679f        // 1/24

#define ROW_BYTES   144                // 64 data halves (128B) + 16 pad
#define ROW_U32     36
#define TILE_BYTES  (128 * ROW_BYTES)               // 18432
#define STAGE_BYTES (2 * TILE_BYTES)                // A+B = 36864
#define EH          136                // half epilogue stride
#define EF          132                // float epilogue stride
#define SMEM_SZ     (2 * STAGE_BYTES)               // 73728 (2 CTA/SM)

// ------------------------- scratch (static device mem, zero-init) ----------
__device__ float  g_xnf[(size_t)ROWS * CDIM];      // fp32 xn (residual)
__device__ __half g_xnh[(size_t)ROWS * CDIM];
__device__ __half g_ynh[(size_t)ROWS * CDIM];
__device__ __half g_wqT[(size_t)CPAD * CDIM];      // Wq^T (half, K-major)
__device__ __half g_wkT[(size_t)CPAD * CDIM];      // Wk^T
__device__ __half g_wvT[(size_t)CPAD * CDIM];      // Wv^T
__device__ __half g_wpH[(size_t)CPAD * CDIM];      // Wp (half)
__device__ __half g_w1t[(size_t)CPAD * CDIM];      // (Wq^T Wk)^T  [n][k]
__device__ __half g_w2 [(size_t)CPAD * CDIM];      // Wp*Wv        [n][k]
__device__ __half g_q  [(size_t)ROWS * CDIM];      // q' = yn*W1
__device__ __half g_vt [(size_t)BATCH * CDIM * NTOK];   // v2 transposed [b][n][t]
__device__ __half g_attn[(size_t)BATCH * NTOK * NTOK];  // 67 MB
__device__ float  g_p  [(size_t)ROWS * CDIM];

// ------------------------------- helpers -----------------------------------
__device__ __forceinline__ uint32_t smem_u32(const void* p) {
    uint32_t a;
    asm("{ .reg .u64 t; cvta.to.shared.u64 t, %1; cvt.u32.u64 %0, t; }"
        : "=r"(a) : "l"(p));
    return a;
}
__device__ __forceinline__ void cpa16(uint32_t dst, const void* src, uint32_t sz) {
    asm volatile("cp.async.cg.shared.global [%0], [%1], 16, %2;"
                 :: "r"(dst), "l"(src), "r"(sz) : "memory");
}
__device__ __forceinline__ void cpa_commit() {
    asm volatile("cp.async.commit_group;" ::: "memory");
}
template<int Np> __device__ __forceinline__ void cpa_wait() {
    asm volatile("cp.async.wait_group %0;" :: "n"(Np) : "memory");
}
__device__ __forceinline__ void mma_f16(float* c, const uint32_t* a, const uint32_t* b) {
    asm volatile(
        "mma.sync.aligned.m16n8k16.row.col.f32.f16.f16.f32 "
        "{%0,%1,%2,%3}, {%4,%5,%6,%7}, {%8,%9}, {%0,%1,%2,%3};"
        : "+f"(c[0]), "+f"(c[1]), "+f"(c[2]), "+f"(c[3])
        : "r"(a[0]), "r"(a[1]), "r"(a[2]), "r"(a[3]), "r"(b[0]), "r"(b[1]));
}

// ---------------------------------------------------------------------------
// R8 main loop: 128x128 CTA tile, BK=64, 2 stages, 8 warps (2x4),
// warp tile 64x32 (acc[4][4][4]).
// ---------------------------------------------------------------------------
struct LoopCtx {
    const __half* aPtr;
    const __half* bPtr;
    uint32_t dA, dB, bsz;
};

__device__ __forceinline__ void gemm_loop(
    const LoopCtx& cx, char* smem, int KT,
    int arow, int brow, int tig, float acc[4][4][4])
{
    auto load_stage = [&](int s, int kt) {
        const uint32_t so = (uint32_t)s * STAGE_BYTES;
        const int k0 = kt * 64;
        #pragma unroll
        for (int j = 0; j < 4; j++) {
            cpa16(cx.dA + so + j * 16, cx.aPtr + k0 + j * 8, 16u);
            cpa16(cx.dB + so + j * 16, cx.bPtr + k0 + j * 8, cx.bsz);
        }
    };

    load_stage(0, 0); cpa_commit();
    load_stage(1, 1); cpa_commit();

    for (int kt = 0; kt < KT; kt++) {
        cpa_wait<1>();
        __syncthreads();                 // stage kt&1 landed

        const uint32_t* uAs = (const uint32_t*)(smem + (kt & 1) * STAGE_BYTES);
        const uint32_t* uBs = uAs + 128 * ROW_U32;

        #pragma unroll
        for (int kk = 0; kk < 4; kk++) {
            const int kc = kk * 8 + tig;
            uint32_t af[4][4];
            #pragma unroll
            for (int mt = 0; mt < 4; mt++) {
                const int r = arow + mt * 16;
                af[mt][0] = uAs[r * ROW_U32 + kc];
                af[mt][1] = uAs[(r + 8) * ROW_U32 + kc];
                af[mt][2] = uAs[r * ROW_U32 + kc + 4];
                af[mt][3] = uAs[(r + 8) * ROW_U32 + kc + 4];
            }
            uint32_t bf[4][2];
            #pragma unroll
            for (int nt = 0; nt < 4; nt++) {
                const int n = brow + nt * 8;
                bf[nt][0] = uBs[n * ROW_U32 + kc];
                bf[nt][1] = uBs[n * ROW_U32 + kc + 4];
            }
            #pragma unroll
            for (int mt = 0; mt < 4; mt++)
                #pragma unroll
                for (int nt = 0; nt < 4; nt++)
                    mma_f16(acc[mt][nt], af[mt], bf[nt]);
        }

        __syncthreads();                 // stage kt&1 fully consumed
        if (kt + 2 < KT) load_stage(kt & 1, kt + 2);
        cpa_commit();
    }

    cpa_wait<0>();
    __syncthreads();
}

// ===========================================================================
// Generic GEMM: C[M,N] = A[M,K] @ B[N,K]^T  (half, K-major)
// EPI: 2 = sigmoid(x/24) half store, 3 = fp32 store + bias[n] + resid (z-batched)
// ===========================================================================
template<int EPI>
__global__ __launch_bounds__(256, 2) void mma_gemm(
    const __half* __restrict__ A, const __half* __restrict__ B,
    void* __restrict__ Cv, int M, int N, int K,
    long sAz, long sBz, long sCz, int ldC,
    const float* __restrict__ bias, const float* __restrict__ resid)
{
    extern __shared__ char smem[];
    const uint32_t sb = smem_u32(smem);
    const int tid  = threadIdx.x;
    const int lane = tid & 31;
    const int wid  = tid >> 5;
    const int m0 = blockIdx.y * 128;
    const int n0 = blockIdx.x * 128;
    const int z  = blockIdx.z;

    const int lrow  = tid >> 1;
    const int lhalf = tid & 1;
    const int gn = n0 + lrow;
    LoopCtx cx;
    cx.aPtr = A + (size_t)z * sAz + (size_t)(m0 + lrow) * K + lhalf * 32;
    cx.bsz  = (gn < N) ? 16u : 0u;
    cx.bPtr = B + (size_t)z * sBz + (size_t)(gn < N ? gn : 0) * K + lhalf * 32;
    cx.dA   = sb + (uint32_t)lrow * ROW_BYTES + (uint32_t)lhalf * 64;
    cx.dB   = cx.dA + TILE_BYTES;

    float acc[4][4][4];
    #pragma unroll
    for (int mt = 0; mt < 4; mt++)
        #pragma unroll
        for (int nt = 0; nt < 4; nt++)
            #pragma unroll
            for (int i = 0; i < 4; i++) acc[mt][nt][i] = 0.f;

    const int warp_m = wid & 1;
    const int warp_n = wid >> 1;
    const int gid = lane >> 2;
    const int tig = lane & 3;

    gemm_loop(cx, smem, K >> 6, warp_m * 64 + gid, warp_n * 32 + gid, tig, acc);

    // -------------------------------- epilogue --------------------------------
    if (EPI == 3) {
        float* eb = (float*)smem;        // [128][EF]
        #pragma unroll
        for (int mt = 0; mt < 4; mt++)
            #pragma unroll
            for (int i = 0; i < 4; i++) {
                const int r = warp_m * 64 + mt * 16 + gid + ((i >= 2) ? 8 : 0);
                #pragma unroll
                for (int nt = 0; nt < 4; nt++) {
                    const int c = warp_n * 32 + nt * 8 + tig * 2 + (i & 1);
                    eb[r * EF + c] = acc[mt][nt][i];
                }
            }
        __syncthreads();
        float* C = (float*)Cv + (size_t)z * sCz;
        const float* rz = resid + (size_t)z * sCz;
        #pragma unroll
        for (int it = 0; it < 16; it++) {
            const int lin = it * 256 + tid;
            const int c4 = lin & 31, r = lin >> 5;
            const int n = n0 + c4 * 4;
            if (n < N) {
                float4 v4 = *(const float4*)(eb + r * EF + c4 * 4);
                const float4 bb = *(const float4*)(bias + n);
                const float4 rr = *(const float4*)(rz + (size_t)(m0 + r) * ldC + n);
                v4.x += bb.x + rr.x; v4.y += bb.y + rr.y;
                v4.z += bb.z + rr.z; v4.w += bb.w + rr.w;
                *(float4*)(C + (size_t)(m0 + r) * ldC + n) = v4;
            }
        }
        return;
    }

    __half* ebh = (__half*)smem;         // [128][EH]
    #pragma unroll
    for (int mt = 0; mt < 4; mt++)
        #pragma unroll
        for (int ih = 0; ih < 2; ih++) {
            const int r = warp_m * 64 + mt * 16 + gid + ih * 8;
            #pragma unroll
            for (int nt = 0; nt < 4; nt++) {
                const int c = warp_n * 32 + nt * 8 + tig * 2;
                float v0 = acc[mt][nt][ih * 2], v1 = acc[mt][nt][ih * 2 + 1];
                if (EPI == 2) {
                    v0 = 1.0f / (1.0f + __expf(-v0 * ATT_SCALE));
                    v1 = 1.0f / (1.0f + __expf(-v1 * ATT_SCALE));
                }
                *(__half2*)(ebh + r * EH + c) = __floats2half2_rn(v0, v1);
            }
        }
    __syncthreads();
    {
        __half* C = (__half*)Cv + (size_t)z * sCz;
        #pragma unroll
        for (int it = 0; it < 8; it++) {
            const int lin = it * 256 + tid;
            const int c8 = lin & 15, r = lin >> 4;
            const int n = n0 + c8 * 8;
            if (n < N)
                *(uint4*)(C + (size_t)(m0 + r) * ldC + n) =
                    *(const uint4*)(ebh + r * EH + c8 * 8);
        }
    }
}

// ===========================================================================
// Weight-product GEMM (one launch, grid (5,5,2)):
//  z=0: w1t = wkT @ wqT^T   (= (Wq^T Wk)^T, K-major [n][k])
//  z=1: w2  = wpH @ wvT^T   (= Wp*Wv,       K-major [n][k])
// M=CPAD(640), N=K=CDIM(576). Half store.
// ===========================================================================
__global__ __launch_bounds__(256, 2) void wgemm(
    const __half* __restrict__ wkT, const __half* __restrict__ wqT,
    const __half* __restrict__ wpH, const __half* __restrict__ wvT,
    __half* __restrict__ w1t, __half* __restrict__ w2)
{
    extern __shared__ char smem[];
    const uint32_t sb = smem_u32(smem);
    const int tid  = threadIdx.x;
    const int lane = tid & 31;
    const int wid  = tid >> 5;
    const int m0 = blockIdx.y * 128;
    const int n0 = blockIdx.x * 128;
    const int z  = blockIdx.z;

    const __half* A = (z == 0) ? wkT : wpH;
    const __half* B = (z == 0) ? wqT : wvT;
    __half* C       = (z == 0) ? w1t : w2;

    const int lrow  = tid >> 1;
    const int lhalf = tid & 1;
    const int gn = n0 + lrow;
    LoopCtx cx;
    cx.aPtr = A + (size_t)(m0 + lrow) * CDIM + lhalf * 32;
    cx.bsz  = (gn < CDIM) ? 16u : 0u;
    cx.bPtr = B + (size_t)(gn < CDIM ? gn : 0) * CDIM + lhalf * 32;
    cx.dA   = sb + (uint32_t)lrow * ROW_BYTES + (uint32_t)lhalf * 64;
    cx.dB   = cx.dA + TILE_BYTES;

    float acc[4][4][4];
    #pragma unroll
    for (int mt = 0; mt < 4; mt++)
        #pragma unroll
        for (int nt = 0; nt < 4; nt++)
            #pragma unroll
            for (int i = 0; i < 4; i++) acc[mt][nt][i] = 0.f;

    const int warp_m = wid & 1;
    const int warp_n = wid >> 1;
    const int gid = lane >> 2;
    const int tig = lane & 3;

    gemm_loop(cx, smem, CDIM >> 6, warp_m * 64 + gid, warp_n * 32 + gid, tig, acc);

    __half* ebh = (__half*)smem;         // [128][EH]
    #pragma unroll
    for (int mt = 0; mt < 4; mt++)
        #pragma unroll
        for (int ih = 0; ih < 2; ih++) {
            const int r = warp_m * 64 + mt * 16 + gid + ih * 8;
            #pragma unroll
            for (int nt = 0; nt < 4; nt++) {
                const int c = warp_n * 32 + nt * 8 + tig * 2;
                *(__half2*)(ebh + r * EH + c) =
                    __floats2half2_rn(acc[mt][nt][ih * 2], acc[mt][nt][ih * 2 + 1]);
            }
        }
    __syncthreads();
    #pragma unroll
    for (int it = 0; it < 8; it++) {
        const int lin = it * 256 + tid;
        const int c8 = lin & 15, r = lin >> 4;
        const int n = n0 + c8 * 8;
        if (n < CDIM)
            *(uint4*)(C + (size_t)(m0 + r) * CDIM + n) =
                *(const uint4*)(ebh + r * EH + c8 * 8);
    }
}

// ===========================================================================
// Fused projections: grid (5, 128, 2)
//  z=0: q' = ynh @ w1t^T  (half, n-major)
//  z=1: v2 = xnh @ w2^T   (half, TRANSPOSED store -> vt[b][n][t])
// ===========================================================================
__global__ __launch_bounds__(256, 2) void proj_gemm(
    const __half* __restrict__ xnh, const __half* __restrict__ ynh,
    const __half* __restrict__ w1t, const __half* __restrict__ w2,
    __half* __restrict__ q, __half* __restrict__ vt)
{
    extern __shared__ char smem[];
    const uint32_t sb = smem_u32(smem);
    const int tid  = threadIdx.x;
    const int lane = tid & 31;
    const int wid  = tid >> 5;
    const int m0 = blockIdx.y * 128;
    const int n0 = blockIdx.x * 128;
    const int z  = blockIdx.z;

    const __half* A = (z == 0) ? ynh : xnh;
    const __half* B = (z == 0) ? w1t : w2;

    const int lrow  = tid >> 1;
    const int lhalf = tid & 1;
    const int gn = n0 + lrow;
    LoopCtx cx;
    cx.aPtr = A + (size_t)(m0 + lrow) * CDIM + lhalf * 32;
    cx.bsz  = (gn < CDIM) ? 16u : 0u;
    cx.bPtr = B + (size_t)(gn < CDIM ? gn : 0) * CDIM + lhalf * 32;
    cx.dA   = sb + (uint32_t)lrow * ROW_BYTES + (uint32_t)lhalf * 64;
    cx.dB   = cx.dA + TILE_BYTES;

    float acc[4][4][4];
    #pragma unroll
    for (int mt = 0; mt < 4; mt++)
        #pragma unroll
        for (int nt = 0; nt < 4; nt++)
            #pragma unroll
            for (int i = 0; i < 4; i++) acc[mt][nt][i] = 0.f;

    const int warp_m = wid & 1;
    const int warp_n = wid >> 1;
    const int gid = lane >> 2;
    const int tig = lane & 3;

    gemm_loop(cx, smem, CDIM >> 6, warp_m * 64 + gid, warp_n * 32 + gid, tig, acc);

    __half* ebh = (__half*)smem;
    if (z == 1) {
        // transposed staging: ebh[n_local][t_local] (stride EH)
        #pragma unroll
        for (int mt = 0; mt < 4; mt++)
            #pragma unroll
            for (int i = 0; i < 4; i++) {
                const int r = warp_m * 64 + mt * 16 + gid + ((i >= 2) ? 8 : 0);
                #pragma unroll
                for (int nt = 0; nt < 4; nt++) {
                    const int c = warp_n * 32 + nt * 8 + tig * 2 + (i & 1);
                    ebh[c * EH + r] = __float2half_rn(acc[mt][nt][i]);
                }
            }
        __syncthreads();
        const int b = m0 >> 11, t0 = m0 & 2047;
        __half* vb = vt + (size_t)b * CDIM * NTOK + t0;
        #pragma unroll
        for (int it = 0; it < 8; it++) {
            const int lin = it * 256 + tid;
            const int t8 = (lin & 15) * 8, n = lin >> 4;
            if (n0 + n < CDIM)
                *(uint4*)(vb + (size_t)(n0 + n) * NTOK + t8) =
                    *(const uint4*)(ebh + n * EH + t8);
        }
        return;
    }

    #pragma unroll
    for (int mt = 0; mt < 4; mt++)
        #pragma unroll
        for (int ih = 0; ih < 2; ih++) {
            const int r = warp_m * 64 + mt * 16 + gid + ih * 8;
            #pragma unroll
            for (int nt = 0; nt < 4; nt++) {
                const int c = warp_n * 32 + nt * 8 + tig * 2;
                *(__half2*)(ebh + r * EH + c) =
                    __floats2half2_rn(acc[mt][nt][ih * 2], acc[mt][nt][ih * 2 + 1]);
            }
        }
    __syncthreads();
    #pragma unroll
    for (int it = 0; it < 8; it++) {
        const int lin = it * 256 + tid;
        const int c8 = lin & 15, r = lin >> 4;
        const int n = n0 + c8 * 8;
        if (n < CDIM)
            *(uint4*)(q + (size_t)(m0 + r) * CDIM + n) =
                *(const uint4*)(ebh + r * EH + c8 * 8);
    }
}

// ===========================================================================
// Fused dual LayerNorm: grid (ROWS, 2). y=0: x -> (xnf, xnh); y=1: y -> ynh.
// ===========================================================================
__global__ __launch_bounds__(256) void ln2_kernel(
    const float* __restrict__ x, const float* __restrict__ y,
    const float* __restrict__ gx, const float* __restrict__ bx,
    const float* __restrict__ gy, const float* __restrict__ by,
    float* __restrict__ xnf, __half* __restrict__ xnh,
    __half* __restrict__ ynh)
{
    const int which = blockIdx.y;
    const long row = blockIdx.x;
    const float* xr = ((which == 0) ? x : y) + row * (long)CDIM;
    const float* g  = (which == 0) ? gx : gy;
    const float* b  = (which == 0) ? bx : by;
    const int t = threadIdx.x;

    float v0 = xr[t];
    float v1 = xr[t + 256];
    float v2 = (t < 64) ? xr[t + 512] : 0.f;

    float s  = v0 + v1 + v2;
    float ss = v0 * v0 + v1 * v1 + v2 * v2;
    #pragma unroll
    for (int o = 16; o > 0; o >>= 1) {
        s  += __shfl_xor_sync(0xFFFFFFFFu, s,  o);
        ss += __shfl_xor_sync(0xFFFFFFFFu, ss, o);
    }
    __shared__ float sh_s[8], sh_ss[8];
    const int w = t >> 5, l = t & 31;
    if (l == 0) { sh_s[w] = s; sh_ss[w] = ss; }
    __syncthreads();
    float stot = 0.f, sstot = 0.f;
    #pragma unroll
    for (int i = 0; i < 8; i++) { stot += sh_s[i]; sstot += sh_ss[i]; }

    const float inv_n = 1.0f / (float)CDIM;
    const float mean = stot * inv_n;
    const float var  = sstot * inv_n - mean * mean;
    const float rstd = rsqrtf(var + 1e-5f);

    float o0 = (v0 - mean) * rstd * g[t]       + b[t];
    float o1 = (v1 - mean) * rstd * g[t + 256] + b[t + 256];
    float o2 = (t < 64) ? ((v2 - mean) * rstd * g[t + 512] + b[t + 512]) : 0.f;

    if (which == 0) {
        xnf[row * (long)CDIM + t]       = o0;
        xnf[row * (long)CDIM + t + 256] = o1;
        if (t < 64) xnf[row * (long)CDIM + t + 512] = o2;
        xnh[row * (long)CDIM + t]       = __float2half_rn(o0);
        xnh[row * (long)CDIM + t + 256] = __float2half_rn(o1);
        if (t < 64) xnh[row * (long)CDIM + t + 512] = __float2half_rn(o2);
    } else {
        ynh[row * (long)CDIM + t]       = __float2half_rn(o0);
        ynh[row * (long)CDIM + t + 256] = __float2half_rn(o1);
        if (t < 64) ynh[row * (long)CDIM + t + 512] = __float2half_rn(o2);
    }
}

// Final LayerNorm: fp32 in -> fp32 out
__global__ __launch_bounds__(256) void ln_kernel(
    const float* __restrict__ x, const float* __restrict__ g,
    const float* __restrict__ b, float* __restrict__ out_f)
{
    const long row = blockIdx.x;
    const float* xr = x + row * (long)CDIM;
    const int t = threadIdx.x;

    float v0 = xr[t];
    float v1 = xr[t + 256];
    float v2 = (t < 64) ? xr[t + 512] : 0.f;

    float s  = v0 + v1 + v2;
    float ss = v0 * v0 + v1 * v1 + v2 * v2;
    #pragma unroll
    for (int o = 16; o > 0; o >>= 1) {
        s  += __shfl_xor_sync(0xFFFFFFFFu, s,  o);
        ss += __shfl_xor_sync(0xFFFFFFFFu, ss, o);
    }
    __shared__ float sh_s[8], sh_ss[8];
    const int w = t >> 5, l = t & 31;
    if (l == 0) { sh_s[w] = s; sh_ss[w] = ss; }
    __syncthreads();
    float stot = 0.f, sstot = 0.f;
    #pragma unroll
    for (int i = 0; i < 8; i++) { stot += sh_s[i]; sstot += sh_ss[i]; }

    const float inv_n = 1.0f / (float)CDIM;
    const float mean = stot * inv_n;
    const float var  = sstot * inv_n - mean * mean;
    const float rstd = rsqrtf(var + 1e-5f);

    out_f[row * (long)CDIM + t]       = (v0 - mean) * rstd * g[t]       + b[t];
    out_f[row * (long)CDIM + t + 256] = (v1 - mean) * rstd * g[t + 256] + b[t + 256];
    if (t < 64)
        out_f[row * (long)CDIM + t + 512] = (v2 - mean) * rstd * g[t + 512] + b[t + 512];
}

// ===========================================================================
// Weight convert: grid (18, 18, 4), block 256 (32x8 tiles).
//  z=0..2: transpose-convert Wq,Wk,Wv -> wqT,wkT,wvT (half, [col][row])
//  z=3:    straight convert Wp -> wpH
// ===========================================================================
__global__ __launch_bounds__(256) void tconv(
    const float* __restrict__ Wq, const float* __restrict__ Wk,
    const float* __restrict__ Wv, const float* __restrict__ Wp,
    __half* __restrict__ wqT, __half* __restrict__ wkT,
    __half* __restrict__ wvT, __half* __restrict__ wpH)
{
    __shared__ float tile[32][33];
    const int zz = blockIdx.z;
    const float* src = (zz == 0) ? Wq : (zz == 1) ? Wk : (zz == 2) ? Wv : Wp;
    __half* dst      = (zz == 0) ? wqT : (zz == 1) ? wkT : (zz == 2) ? wvT : wpH;
    const int bx = blockIdx.x * 32, by = blockIdx.y * 32;
    const int tx = threadIdx.x & 31, ty = threadIdx.x >> 5;

    if (zz < 3) {
        #pragma unroll
        for (int i = 0; i < 32; i += 8)
            tile[ty + i][tx] = src[(size_t)(by + ty + i) * CDIM + bx + tx];
        __syncthreads();
        #pragma unroll
        for (int i = 0; i < 32; i += 8)
            dst[(size_t)(bx + ty + i) * CDIM + by + tx] =
                __float2half_rn(tile[tx][ty + i]);
    } else {
        #pragma unroll
        for (int i = 0; i < 32; i += 8)
            dst[(size_t)(by + ty + i) * CDIM + bx + tx] =
                __float2half_rn(src[(size_t)(by + ty + i) * CDIM + bx + tx]);
    }
}

// ===========================================================================
extern "C" void kernel_launch(void* const* d_in, const int* in_sizes, int n_in,
                              void* d_out, int out_size)
{
    const float* x  = (const float*)d_in[0];
    const float* y  = (const float*)d_in[1];
    const float* Wq = (const float*)d_in[2];
    const float* Wk = (const float*)d_in[3];
    const float* Wv = (const float*)d_in[4];
    const float* Wp = (const float*)d_in[5];
    const float* bp = (const float*)d_in[6];
    const float* gx = (const float*)d_in[7];
    const float* bx = (const float*)d_in[8];
    const float* gy = (const float*)d_in[9];
    const float* by = (const float*)d_in[10];
    const float* gz = (const float*)d_in[11];
    const float* bz = (const float*)d_in[12];
    float* out = (float*)d_out;

    float *xnf, *p;
    __half *xnh, *ynh, *wqT, *wkT, *wvT, *wpH, *w1t, *w2, *q, *vt, *attn;
    cudaGetSymbolAddress((void**)&xnf, g_xnf);
    cudaGetSymbolAddress((void**)&xnh, g_xnh);
    cudaGetSymbolAddress((void**)&ynh, g_ynh);
    cudaGetSymbolAddress((void**)&wqT, g_wqT);
    cudaGetSymbolAddress((void**)&wkT, g_wkT);
    cudaGetSymbolAddress((void**)&wvT, g_wvT);
    cudaGetSymbolAddress((void**)&wpH, g_wpH);
    cudaGetSymbolAddress((void**)&w1t, g_w1t);
    cudaGetSymbolAddress((void**)&w2,  g_w2);
    cudaGetSymbolAddress((void**)&q,   g_q);
    cudaGetSymbolAddress((void**)&vt,  g_vt);
    cudaGetSymbolAddress((void**)&attn,g_attn);
    cudaGetSymbolAddress((void**)&p,   g_p);

    cudaFuncSetAttribute(mma_gemm<2>, cudaFuncAttributeMaxDynamicSharedMemorySize, SMEM_SZ);
    cudaFuncSetAttribute(mma_gemm<3>, cudaFuncAttributeMaxDynamicSharedMemorySize, SMEM_SZ);
    cudaFuncSetAttribute(proj_gemm,   cudaFuncAttributeMaxDynamicSharedMemorySize, SMEM_SZ);
    cudaFuncSetAttribute(wgemm,       cudaFuncAttributeMaxDynamicSharedMemorySize, SMEM_SZ);

    // 1. fused LayerNorms (x -> xnf+xnh, y -> ynh)
    {
        dim3 grid(ROWS, 2, 1);
        ln2_kernel<<<grid, 256>>>(x, y, gx, bx, gy, by, xnf, xnh, ynh);
    }

    // 2. weight converts (transposed Wq/Wk/Wv + straight Wp)
    {
        dim3 grid(18, 18, 4);
        tconv<<<grid, 256>>>(Wq, Wk, Wv, Wp, wqT, wkT, wvT, wpH);
    }

    // 3. weight products: w1t = (Wq^T Wk)^T, w2 = Wp*Wv  (one launch)
    {
        dim3 grid(5, 5, 2);
        wgemm<<<grid, 256, SMEM_SZ>>>(wkT, wqT, wpH, wvT, w1t, w2);
    }

    // 4. fused projections: q' = yn*W1 (z=0), vt = (xn*W2^T)^T (z=1)
    {
        dim3 grid(5, 128, 2);
        proj_gemm<<<grid, 256, SMEM_SZ>>>(xnh, ynh, w1t, w2, q, vt);
    }

    // 5. attn = sigmoid(q' @ xn^T / 24) per batch, half
    {
        dim3 grid(16, 16, BATCH);
        mma_gemm<2><<<grid, 256, SMEM_SZ>>>(q, xnh, attn, NTOK, NTOK, CDIM,
            (long)NTOK * CDIM, (long)NTOK * CDIM, (long)NTOK * NTOK, NTOK, nullptr, nullptr);
    }

    // 6. P = attn @ vt^T + bp + xn  (fp32, per batch)
    {
        dim3 grid(5, 16, BATCH);
        mma_gemm<3><<<grid, 256, SMEM_SZ>>>(attn, vt, p, NTOK, CDIM, NTOK,
            (long)NTOK * NTOK, (long)CDIM * NTOK, (long)NTOK * CDIM, CDIM, bp, xnf);
    }

    // 7. out = LN(P)
    ln_kernel<<<ROWS, 256>>>(p, gz, bz, out);
}